// round 15
// baseline (speedup 1.0000x reference)
#include <cuda_runtime.h>
#include <math.h>

#define LAMDA 0.1f
#define T_AVG 8192
#define THREADS 256
#define BLOCKS (148 * 4)
#define T8 (T_AVG / 8)   // 1024 float8 = cyclic offset in F8 units

// Accumulators: zero at module load; reset by the last block each launch,
// so every graph replay starts clean. Counter self-wraps via atomicInc.
__device__ float g_acc0;
__device__ float g_acc1;
__device__ unsigned int g_count;

struct F8 { float4 lo, hi; };

__device__ __forceinline__ F8 unpack(unsigned long long x0, unsigned long long x1,
                                     unsigned long long x2, unsigned long long x3) {
    F8 r;
    r.lo.x = __uint_as_float((unsigned)x0);
    r.lo.y = __uint_as_float((unsigned)(x0 >> 32));
    r.lo.z = __uint_as_float((unsigned)x1);
    r.lo.w = __uint_as_float((unsigned)(x1 >> 32));
    r.hi.x = __uint_as_float((unsigned)x2);
    r.hi.y = __uint_as_float((unsigned)(x2 >> 32));
    r.hi.z = __uint_as_float((unsigned)x3);
    r.hi.w = __uint_as_float((unsigned)(x3 >> 32));
    return r;
}

// 256-bit loads: half the LDG instruction count of float4 -> fewer L1
// wavefronts, better per-instruction MLP at the DRAM roofline.
__device__ __forceinline__ F8 ld8(const F8* p) {
    unsigned long long x0, x1, x2, x3;
    asm("ld.global.nc.v4.b64 {%0,%1,%2,%3}, [%4];"
        : "=l"(x0), "=l"(x1), "=l"(x2), "=l"(x3) : "l"(p));
    return unpack(x0, x1, x2, x3);
}
__device__ __forceinline__ F8 ld8_cs(const F8* p) {
    unsigned long long x0, x1, x2, x3;
    asm("ld.global.cs.nc.v4.b64 {%0,%1,%2,%3}, [%4];"
        : "=l"(x0), "=l"(x1), "=l"(x2), "=l"(x3) : "l"(p));
    return unpack(x0, x1, x2, x3);
}

__device__ __forceinline__ float sq4(float4 a, float4 b) {
    float d0 = a.x - b.x;
    float d1 = a.y - b.y;
    float d2 = a.z - b.z;
    float d3 = a.w - b.w;
    return d0 * d0 + d1 * d1 + d2 * d2 + d3 * d3;
}
__device__ __forceinline__ float sq8(F8 a, F8 b) {
    return sq4(a.lo, b.lo) + sq4(a.hi, b.hi);
}

// R5 structure (best measured): contiguous per-block chunks, three streams
// (in, in+T, tg), streaming hint on tg. Upgraded to 256-bit loads.
__global__ void __launch_bounds__(THREADS, 4) fused_loss_kernel(
    const F8* __restrict__ in,
    const F8* __restrict__ tg,
    float* __restrict__ out,
    int n8, int lim8 /* = n8 - T8 */, int chunk,
    float inv_n, int nSteps)
{
    float s_mse = 0.0f;
    float s_cyc = 0.0f;

    const int base = blockIdx.x * chunk;
    const int end = min(base + chunk, n8);
    const int end_cyc = min(end, lim8);
    int i = base + threadIdx.x;

    // Main 2x-unrolled path (both terms; 6 front-batched 32B LDG.256).
    for (; i + THREADS < end_cyc; i += 2 * THREADS) {
        F8 a0 = ld8(&in[i]);
        F8 a1 = ld8(&in[i + THREADS]);
        F8 c0 = ld8(&in[i + T8]);
        F8 c1 = ld8(&in[i + THREADS + T8]);
        F8 b0 = ld8_cs(&tg[i]);
        F8 b1 = ld8_cs(&tg[i + THREADS]);
        s_mse += sq8(a0, b0);
        s_mse += sq8(a1, b1);
        s_cyc += sq8(a0, c0);
        s_cyc += sq8(a1, c1);
    }
    // Tail of the cyc region.
    for (; i < end_cyc; i += THREADS) {
        F8 a = ld8(&in[i]);
        F8 b = ld8_cs(&tg[i]);
        F8 c = ld8(&in[i + T8]);
        s_mse += sq8(a, b);
        s_cyc += sq8(a, c);
    }
    // MSE-only region (last T elements; only the final data block).
    for (; i < end; i += THREADS) {
        F8 a = ld8(&in[i]);
        F8 b = ld8_cs(&tg[i]);
        s_mse += sq8(a, b);
    }

    // Warp reduction
    #pragma unroll
    for (int off = 16; off > 0; off >>= 1) {
        s_mse += __shfl_xor_sync(0xffffffffu, s_mse, off);
        s_cyc += __shfl_xor_sync(0xffffffffu, s_cyc, off);
    }

    __shared__ float sm_mse[THREADS / 32];
    __shared__ float sm_cyc[THREADS / 32];
    int wid = threadIdx.x >> 5;
    int lid = threadIdx.x & 31;
    if (lid == 0) {
        sm_mse[wid] = s_mse;
        sm_cyc[wid] = s_cyc;
    }
    __syncthreads();

    if (threadIdx.x == 0) {
        float bm = sm_mse[0];
        float bc = sm_cyc[0];
        #pragma unroll
        for (int w = 1; w < THREADS / 32; w++) {
            bm += sm_mse[w];
            bc += sm_cyc[w];
        }
        atomicAdd(&g_acc0, bm);
        atomicAdd(&g_acc1, bc);
        __threadfence();
        // atomicInc wraps to 0 when old == gridDim.x-1 -> self-resetting counter
        unsigned int ticket = atomicInc(&g_count, gridDim.x - 1);
        if (ticket == gridDim.x - 1) {
            float tot_mse = atomicAdd(&g_acc0, 0.0f);
            float tot_cyc = atomicAdd(&g_acc1, 0.0f);
            float l1 = (nSteps != 1) ? (LAMDA * sqrtf(tot_cyc)) : 0.0f;
            out[0] = tot_mse * inv_n + l1;
            // Reset for next graph replay.
            g_acc0 = 0.0f;
            g_acc1 = 0.0f;
        }
    }
}

extern "C" void kernel_launch(void* const* d_in, const int* in_sizes, int n_in,
                              void* d_out, int out_size) {
    const float* input  = (const float*)d_in[0];
    const float* target = (const float*)d_in[1];
    float* out = (float*)d_out;

    int n = in_sizes[0];         // 16,777,216
    int n8 = n / 8;
    int T = T_AVG;               // 8192 (fixed for this problem)
    int nSteps = n / T;          // 2048
    int lim8 = n8 - T8;          // (N-1)*T / 8

    // Contiguous per-block chunk, rounded to the 2x block stride so full
    // blocks run only the unrolled path.
    int grp = 2 * THREADS;
    int chunk = (n8 + BLOCKS - 1) / BLOCKS;
    chunk = (chunk + grp - 1) / grp * grp;

    fused_loss_kernel<<<BLOCKS, THREADS>>>(
        (const F8*)input, (const F8*)target, out,
        n8, lim8, chunk, 1.0f / (float)n, nSteps);
}

// round 16
// speedup vs baseline: 1.4776x; 1.4776x over previous
#include <cuda_runtime.h>
#include <math.h>

#define LAMDA 0.1f
#define T_AVG 8192
#define THREADS 512
#define T4 (T_AVG / 4)              // 2048 float4 per "row"
#define STRIPES (T4 / THREADS)      // 4 column stripes
#define SLABS 74                    // row-pair slabs
#define BLOCKS (STRIPES * SLABS)    // 296 = 2 CTAs/SM, single wave

// Accumulators: zero at module load; reset by the last block each launch,
// so every graph replay starts clean. Counter self-wraps via atomicInc.
__device__ float g_acc0;
__device__ float g_acc1;
__device__ unsigned int g_count;

__device__ __forceinline__ float sq4(float4 a, float4 b) {
    float d0 = a.x - b.x;
    float d1 = a.y - b.y;
    float d2 = a.z - b.z;
    float d3 = a.w - b.w;
    return d0 * d0 + d1 * d1 + d2 * d2 + d3 * d3;
}

// View in/tg as [nRows x T4] float4. Thread owns one column; walks row-pairs.
// Every `in` element loaded ONCE (+1 boundary row per slab); carried register
// supplies the inter-pair cyclic diff. `tg` loads use the legacy .lu
// (last-use) cache operator: the line is marked dead after the read, so the
// streaming target frees its L2 ways immediately instead of evicting `in` —
// a different HW mechanism from the (inert) L2::evict_* priority hints.
__global__ void __launch_bounds__(THREADS, 2) fused_loss_kernel(
    const float4* __restrict__ in,
    const float4* __restrict__ tg,
    float* __restrict__ out,
    int nRows, int pairsPerSlab,
    float inv_n, int nSteps)
{
    float s_mse = 0.0f;
    float s_cyc = 0.0f;

    const int stripe = blockIdx.x % STRIPES;
    const int slab = blockIdx.x / STRIPES;
    const int col = stripe * THREADS + threadIdx.x;
    const int totalPairs = nRows >> 1;

    int p0 = slab * pairsPerSlab;
    int p1 = min(p0 + pairsPerSlab, totalPairs);

    if (p0 < p1) {
        const float4* ip = in + col;
        const float4* tp = tg + col;
        int off = 2 * p0 * T4;

        float4 carry;
        // Slab-boundary diff (2p0-1, 2p0): direct load of the previous row.
        if (p0 > 0) {
            carry = ip[off - T4];
        }

        // First pair (peeled: carry diff conditional on p0>0).
        {
            float4 a0 = ip[off];
            float4 a1 = ip[off + T4];
            float4 b0 = __ldlu(&tp[off]);
            float4 b1 = __ldlu(&tp[off + T4]);
            s_mse += sq4(a0, b0);
            s_mse += sq4(a1, b1);
            s_cyc += sq4(a0, a1);
            if (p0 > 0) s_cyc += sq4(carry, a0);
            carry = a1;
            off += 2 * T4;
        }

        // Main pair loop, 2x unrolled (8 front-batched LDG.128s).
        int p = p0 + 1;
        for (; p + 1 < p1; p += 2, off += 4 * T4) {
            float4 a0 = ip[off];
            float4 a1 = ip[off + T4];
            float4 a2 = ip[off + 2 * T4];
            float4 a3 = ip[off + 3 * T4];
            float4 b0 = __ldlu(&tp[off]);
            float4 b1 = __ldlu(&tp[off + T4]);
            float4 b2 = __ldlu(&tp[off + 2 * T4]);
            float4 b3 = __ldlu(&tp[off + 3 * T4]);
            s_mse += sq4(a0, b0);
            s_mse += sq4(a1, b1);
            s_mse += sq4(a2, b2);
            s_mse += sq4(a3, b3);
            s_cyc += sq4(carry, a0);   // (2p-1, 2p)
            s_cyc += sq4(a0, a1);      // (2p, 2p+1)
            s_cyc += sq4(a1, a2);      // (2p+1, 2p+2)
            s_cyc += sq4(a2, a3);      // (2p+2, 2p+3)
            carry = a3;
        }
        // Remaining single pair.
        for (; p < p1; p++, off += 2 * T4) {
            float4 a0 = ip[off];
            float4 a1 = ip[off + T4];
            float4 b0 = __ldlu(&tp[off]);
            float4 b1 = __ldlu(&tp[off + T4]);
            s_mse += sq4(a0, b0);
            s_mse += sq4(a1, b1);
            s_cyc += sq4(carry, a0);
            s_cyc += sq4(a0, a1);
            carry = a1;
        }

        // Generic safety: odd trailing row (not hit for nRows=2048).
        if ((nRows & 1) && p1 == totalPairs) {
            int r = nRows - 1;
            float4 a = ip[r * T4];
            float4 b = __ldlu(&tp[r * T4]);
            s_mse += sq4(a, b);
            s_cyc += sq4(carry, a);   // carry == row nRows-2
        }
    }

    // Warp reduction
    #pragma unroll
    for (int off = 16; off > 0; off >>= 1) {
        s_mse += __shfl_xor_sync(0xffffffffu, s_mse, off);
        s_cyc += __shfl_xor_sync(0xffffffffu, s_cyc, off);
    }

    __shared__ float sm_mse[THREADS / 32];
    __shared__ float sm_cyc[THREADS / 32];
    int wid = threadIdx.x >> 5;
    int lid = threadIdx.x & 31;
    if (lid == 0) {
        sm_mse[wid] = s_mse;
        sm_cyc[wid] = s_cyc;
    }
    __syncthreads();

    if (threadIdx.x == 0) {
        float bm = sm_mse[0];
        float bc = sm_cyc[0];
        #pragma unroll
        for (int w = 1; w < THREADS / 32; w++) {
            bm += sm_mse[w];
            bc += sm_cyc[w];
        }
        atomicAdd(&g_acc0, bm);
        atomicAdd(&g_acc1, bc);
        __threadfence();
        // atomicInc wraps to 0 when old == gridDim.x-1 -> self-resetting counter
        unsigned int ticket = atomicInc(&g_count, gridDim.x - 1);
        if (ticket == gridDim.x - 1) {
            float tot_mse = atomicAdd(&g_acc0, 0.0f);
            float tot_cyc = atomicAdd(&g_acc1, 0.0f);
            float l1 = (nSteps != 1) ? (LAMDA * sqrtf(tot_cyc)) : 0.0f;
            out[0] = tot_mse * inv_n + l1;
            // Reset for next graph replay.
            g_acc0 = 0.0f;
            g_acc1 = 0.0f;
        }
    }
}

extern "C" void kernel_launch(void* const* d_in, const int* in_sizes, int n_in,
                              void* d_out, int out_size) {
    const float* input  = (const float*)d_in[0];
    const float* target = (const float*)d_in[1];
    float* out = (float*)d_out;

    int n = in_sizes[0];         // 16,777,216
    int n4 = n / 4;
    int T = T_AVG;               // 8192 (fixed for this problem)
    int nSteps = n / T;          // 2048
    int nRows = n4 / T4;         // 2048 rows of T4 float4
    int totalPairs = nRows / 2;  // 1024
    int pairsPerSlab = (totalPairs + SLABS - 1) / SLABS;  // 14

    fused_loss_kernel<<<BLOCKS, THREADS>>>(
        (const float4*)input, (const float4*)target, out,
        nRows, pairsPerSlab, 1.0f / (float)n, nSteps);
}